// round 1
// baseline (speedup 1.0000x reference)
#include <cuda_runtime.h>

#define D 128
#define MAX_N 100000
#define TILE_ROWS 64
#define GEMM_SMEM ((D*D + TILE_ROWS*D) * (int)sizeof(float))  // 96 KB

// Scratch for A@x and A^2@x (allocation-free rule: __device__ globals)
__device__ float g_hop1[(size_t)MAX_N * D];
__device__ float g_hop2[(size_t)MAX_N * D];

// ---------------------------------------------------------------------------
// SpMM scatter: y[row[e], :] += vals[e] * x[col[e], :]
// One warp per edge; lane handles 4 consecutive floats (float4).
// Scatter via red.global.add.v4.f32 (sm_90+), 16B per op.
// ---------------------------------------------------------------------------
__global__ void spmm_scatter_kernel(const float* __restrict__ x,
                                    float* __restrict__ y,
                                    const float* __restrict__ vals,
                                    const int* __restrict__ row,
                                    const int* __restrict__ col,
                                    int n_edges) {
    int gtid = blockIdx.x * blockDim.x + threadIdx.x;
    int e    = gtid >> 5;
    int lane = gtid & 31;
    if (e >= n_edges) return;

    int   r = __ldg(&row[e]);
    int   c = __ldg(&col[e]);
    float v = __ldg(&vals[e]);

    float4 xv = ((const float4*)x)[(size_t)c * (D / 4) + lane];
    float4 p;
    p.x = v * xv.x; p.y = v * xv.y; p.z = v * xv.z; p.w = v * xv.w;

    float* addr = y + (size_t)r * D + lane * 4;
    asm volatile("red.global.add.v4.f32 [%0], {%1, %2, %3, %4};"
                 :: "l"(addr), "f"(p.x), "f"(p.y), "f"(p.z), "f"(p.w)
                 : "memory");
}

// ---------------------------------------------------------------------------
// Fused GEMM + bias + relu + per-row moment-norm + affine (+ accumulate).
//   vw  = relu(V @ W + b)            (V: n x 128, W: 128 x 128)
//   out(+)= sc * (vw - mean_row) * rsqrt(var_row + 1e-9) + off
// Block: 256 threads = (32 col-quads) x (8 row-groups); tile 64 rows x 128 cols.
// Each thread: 8 rows x 4 cols accumulators. Warp ty owns 8 complete rows,
// so row moments are a pure warp shuffle reduction.
// ---------------------------------------------------------------------------
__global__ void __launch_bounds__(256, 2)
gemm_norm_kernel(const float* __restrict__ V,
                 const float* __restrict__ W,
                 const float* __restrict__ b,
                 const float* __restrict__ off,
                 const float* __restrict__ sc,
                 float* __restrict__ out,
                 int n_rows, int accumulate) {
    extern __shared__ float sh[];
    float* Wsh = sh;                  // 128 x 128
    float* Vsh = sh + D * D;          // 64 x 128

    const int tx  = threadIdx.x;      // 0..31  (col quad)
    const int ty  = threadIdx.y;      // 0..7   (row group)
    const int tid = ty * 32 + tx;
    const int row0 = blockIdx.x * TILE_ROWS;

    // Stage W (4096 float4) and V tile (64 rows x 32 float4)
    #pragma unroll
    for (int i = tid; i < D * D / 4; i += 256)
        ((float4*)Wsh)[i] = ((const float4*)W)[i];

    for (int i = tid; i < TILE_ROWS * (D / 4); i += 256) {
        int r = i >> 5, c = i & 31;
        float4 v;
        if (row0 + r < n_rows)
            v = ((const float4*)V)[(size_t)(row0 + r) * (D / 4) + c];
        else
            v = make_float4(0.f, 0.f, 0.f, 0.f);
        ((float4*)Vsh)[r * (D / 4) + c] = v;
    }
    __syncthreads();

    float acc[8][4];
    #pragma unroll
    for (int r = 0; r < 8; r++)
        #pragma unroll
        for (int c = 0; c < 4; c++) acc[r][c] = 0.f;

    #pragma unroll 8
    for (int k = 0; k < D; k++) {
        float4 w = *(const float4*)&Wsh[k * D + tx * 4];
        #pragma unroll
        for (int r = 0; r < 8; r++) {
            float v = Vsh[(ty * 8 + r) * D + k];   // warp-broadcast
            acc[r][0] = fmaf(v, w.x, acc[r][0]);
            acc[r][1] = fmaf(v, w.y, acc[r][1]);
            acc[r][2] = fmaf(v, w.z, acc[r][2]);
            acc[r][3] = fmaf(v, w.w, acc[r][3]);
        }
    }

    const float4 bv   = ((const float4*)b)[tx];
    const float4 scv  = ((const float4*)sc)[tx];
    const float4 offv = ((const float4*)off)[tx];
    const float inv_d = 1.0f / (float)D;

    #pragma unroll
    for (int r = 0; r < 8; r++) {
        int row = row0 + ty * 8 + r;

        float4 vw;
        vw.x = fmaxf(acc[r][0] + bv.x, 0.f);
        vw.y = fmaxf(acc[r][1] + bv.y, 0.f);
        vw.z = fmaxf(acc[r][2] + bv.z, 0.f);
        vw.w = fmaxf(acc[r][3] + bv.w, 0.f);

        float s  = vw.x + vw.y + vw.z + vw.w;
        float sq = vw.x * vw.x + vw.y * vw.y + vw.z * vw.z + vw.w * vw.w;
        #pragma unroll
        for (int o = 16; o > 0; o >>= 1) {
            s  += __shfl_xor_sync(0xffffffffu, s,  o);
            sq += __shfl_xor_sync(0xffffffffu, sq, o);
        }

        float mean = s * inv_d;
        float var  = sq * inv_d - mean * mean;
        float inv  = rsqrtf(var + 1e-9f);

        float4 res;
        res.x = scv.x * (vw.x - mean) * inv + offv.x;
        res.y = scv.y * (vw.y - mean) * inv + offv.y;
        res.z = scv.z * (vw.z - mean) * inv + offv.z;
        res.w = scv.w * (vw.w - mean) * inv + offv.w;

        if (row < n_rows) {
            float4* po = (float4*)&out[(size_t)row * D + tx * 4];
            if (accumulate) {
                float4 cur = *po;
                res.x += cur.x; res.y += cur.y; res.z += cur.z; res.w += cur.w;
            }
            *po = res;
        }
    }
}

// ---------------------------------------------------------------------------
extern "C" void kernel_launch(void* const* d_in, const int* in_sizes, int n_in,
                              void* d_out, int out_size) {
    const float* vecs = (const float*)d_in[0];
    const float* vals = (const float*)d_in[1];
    const int*   row  = (const int*)d_in[2];
    const int*   col  = (const int*)d_in[3];
    const float* W0 = (const float*)d_in[4];
    const float* b0 = (const float*)d_in[5];
    const float* off0 = (const float*)d_in[6];
    const float* sc0  = (const float*)d_in[7];
    const float* W1 = (const float*)d_in[8];
    const float* b1 = (const float*)d_in[9];
    const float* off1 = (const float*)d_in[10];
    const float* sc1  = (const float*)d_in[11];
    const float* W2 = (const float*)d_in[12];
    const float* b2 = (const float*)d_in[13];
    const float* off2 = (const float*)d_in[14];
    const float* sc2  = (const float*)d_in[15];
    float* out = (float*)d_out;

    const int n_edges = in_sizes[1];
    const int n_rows  = in_sizes[0] / D;

    float *hop1, *hop2;
    cudaGetSymbolAddress((void**)&hop1, g_hop1);
    cudaGetSymbolAddress((void**)&hop2, g_hop2);
    cudaFuncSetAttribute(gemm_norm_kernel,
                         cudaFuncAttributeMaxDynamicSharedMemorySize, GEMM_SMEM);

    const size_t hop_bytes = (size_t)n_rows * D * sizeof(float);
    cudaMemsetAsync(hop1, 0, hop_bytes);
    cudaMemsetAsync(hop2, 0, hop_bytes);

    const int spmm_threads = 256;
    const long long total = (long long)n_edges * 32;
    const int spmm_blocks = (int)((total + spmm_threads - 1) / spmm_threads);

    spmm_scatter_kernel<<<spmm_blocks, spmm_threads>>>(vecs, hop1, vals, row, col, n_edges);
    spmm_scatter_kernel<<<spmm_blocks, spmm_threads>>>(hop1, hop2, vals, row, col, n_edges);

    const int gemm_blocks = (n_rows + TILE_ROWS - 1) / TILE_ROWS;
    dim3 gb(32, 8);
    gemm_norm_kernel<<<gemm_blocks, gb, GEMM_SMEM>>>(vecs, W0, b0, off0, sc0, out, n_rows, 0);
    gemm_norm_kernel<<<gemm_blocks, gb, GEMM_SMEM>>>(hop1, W1, b1, off1, sc1, out, n_rows, 1);
    gemm_norm_kernel<<<gemm_blocks, gb, GEMM_SMEM>>>(hop2, W2, b2, off2, sc2, out, n_rows, 1);
}

// round 2
// speedup vs baseline: 1.0636x; 1.0636x over previous
#include <cuda_runtime.h>

#define D 128
#define MAX_N 100000
#define TILE_ROWS 64
#define GEMM_SMEM ((D*D + TILE_ROWS*D) * (int)sizeof(float))  // 96 KB

// Scratch for A@x and A^2@x (allocation-free rule: __device__ globals)
__device__ float g_hop1[(size_t)MAX_N * D];
__device__ float g_hop2[(size_t)MAX_N * D];

// ---------------------------------------------------------------------------
// Packed fp32x2 helpers (sm_103a: fma.rn.f32x2 — 2 fp32 FMAs per fma-pipe slot)
// ---------------------------------------------------------------------------
__device__ __forceinline__ unsigned long long ffma2(unsigned long long a,
                                                    unsigned long long b,
                                                    unsigned long long c) {
    unsigned long long d;
    asm("fma.rn.f32x2 %0, %1, %2, %3;" : "=l"(d) : "l"(a), "l"(b), "l"(c));
    return d;
}
__device__ __forceinline__ unsigned long long splat2(float x) {
    unsigned long long d;
    asm("mov.b64 %0, {%1, %1};" : "=l"(d) : "f"(x));
    return d;
}
__device__ __forceinline__ float2 unpack2(unsigned long long v) {
    float lo, hi;
    asm("mov.b64 {%0, %1}, %2;" : "=f"(lo), "=f"(hi) : "l"(v));
    return make_float2(lo, hi);
}

// ---------------------------------------------------------------------------
// SpMM scatter: y[row[e], :] += vals[e] * x[col[e], :]
// One warp per edge; lane handles 4 consecutive floats (float4).
// Scatter via red.global.add.v4.f32 (sm_90+), 16B per op.
// ---------------------------------------------------------------------------
__global__ void spmm_scatter_kernel(const float* __restrict__ x,
                                    float* __restrict__ y,
                                    const float* __restrict__ vals,
                                    const int* __restrict__ row,
                                    const int* __restrict__ col,
                                    int n_edges) {
    int gtid = blockIdx.x * blockDim.x + threadIdx.x;
    int e    = gtid >> 5;
    int lane = gtid & 31;
    if (e >= n_edges) return;

    int   r = __ldg(&row[e]);
    int   c = __ldg(&col[e]);
    float v = __ldg(&vals[e]);

    float4 xv = ((const float4*)x)[(size_t)c * (D / 4) + lane];
    float4 p;
    p.x = v * xv.x; p.y = v * xv.y; p.z = v * xv.z; p.w = v * xv.w;

    float* addr = y + (size_t)r * D + lane * 4;
    asm volatile("red.global.add.v4.f32 [%0], {%1, %2, %3, %4};"
                 :: "l"(addr), "f"(p.x), "f"(p.y), "f"(p.z), "f"(p.w)
                 : "memory");
}

// ---------------------------------------------------------------------------
// Fused GEMM + bias + relu + per-row moment-norm + affine (+ accumulate).
//   vw  = relu(V @ W + b)            (V: n x 128, W: 128 x 128)
//   out(+)= sc * (vw - mean_row) * rsqrt(var_row + 1e-9) + off
// Block: 256 threads = (32 col-quads) x (8 row-groups); tile 64 rows x 128 cols.
// Each thread: 8 rows x 4 cols, held as 8x2 packed f32x2 accumulators.
// Inner loop uses fma.rn.f32x2: 16 fma-pipe instrs per k instead of 32.
// ---------------------------------------------------------------------------
__global__ void __launch_bounds__(256, 2)
gemm_norm_kernel(const float* __restrict__ V,
                 const float* __restrict__ W,
                 const float* __restrict__ b,
                 const float* __restrict__ off,
                 const float* __restrict__ sc,
                 float* __restrict__ out,
                 int n_rows, int accumulate) {
    extern __shared__ float sh[];
    float* Wsh = sh;                  // 128 x 128
    float* Vsh = sh + D * D;          // 64 x 128

    const int tx  = threadIdx.x;      // 0..31  (col quad)
    const int ty  = threadIdx.y;      // 0..7   (row group)
    const int tid = ty * 32 + tx;
    const int row0 = blockIdx.x * TILE_ROWS;

    // Stage W (4096 float4) and V tile (64 rows x 32 float4)
    #pragma unroll
    for (int i = tid; i < D * D / 4; i += 256)
        ((float4*)Wsh)[i] = ((const float4*)W)[i];

    for (int i = tid; i < TILE_ROWS * (D / 4); i += 256) {
        int r = i >> 5, c = i & 31;
        float4 v;
        if (row0 + r < n_rows)
            v = ((const float4*)V)[(size_t)(row0 + r) * (D / 4) + c];
        else
            v = make_float4(0.f, 0.f, 0.f, 0.f);
        ((float4*)Vsh)[r * (D / 4) + c] = v;
    }
    __syncthreads();

    unsigned long long acc[8][2];
    #pragma unroll
    for (int r = 0; r < 8; r++) {
        acc[r][0] = 0ull;
        acc[r][1] = 0ull;
    }

    // k-loop in chunks of 4: load V as float4 per row (broadcast LDS.128),
    // W pre-paired straight from smem (one LDS.128 -> two f32x2 operands).
    #pragma unroll 4
    for (int k4 = 0; k4 < D / 4; k4++) {
        float4 vv[8];
        #pragma unroll
        for (int r = 0; r < 8; r++)
            vv[r] = *(const float4*)&Vsh[(ty * 8 + r) * D + k4 * 4];

        #pragma unroll
        for (int kk = 0; kk < 4; kk++) {
            const ulonglong2 w2 = *(const ulonglong2*)&Wsh[(k4 * 4 + kk) * D + tx * 4];
            #pragma unroll
            for (int r = 0; r < 8; r++) {
                float v = (kk == 0) ? vv[r].x : (kk == 1) ? vv[r].y
                        : (kk == 2) ? vv[r].z : vv[r].w;
                unsigned long long vp = splat2(v);
                acc[r][0] = ffma2(vp, w2.x, acc[r][0]);
                acc[r][1] = ffma2(vp, w2.y, acc[r][1]);
            }
        }
    }

    const float4 bv   = ((const float4*)b)[tx];
    const float4 scv  = ((const float4*)sc)[tx];
    const float4 offv = ((const float4*)off)[tx];
    const float inv_d = 1.0f / (float)D;

    #pragma unroll
    for (int r = 0; r < 8; r++) {
        int row = row0 + ty * 8 + r;

        float2 a01 = unpack2(acc[r][0]);
        float2 a23 = unpack2(acc[r][1]);

        float4 vw;
        vw.x = fmaxf(a01.x + bv.x, 0.f);
        vw.y = fmaxf(a01.y + bv.y, 0.f);
        vw.z = fmaxf(a23.x + bv.z, 0.f);
        vw.w = fmaxf(a23.y + bv.w, 0.f);

        float s  = vw.x + vw.y + vw.z + vw.w;
        float sq = vw.x * vw.x + vw.y * vw.y + vw.z * vw.z + vw.w * vw.w;
        #pragma unroll
        for (int o = 16; o > 0; o >>= 1) {
            s  += __shfl_xor_sync(0xffffffffu, s,  o);
            sq += __shfl_xor_sync(0xffffffffu, sq, o);
        }

        float mean = s * inv_d;
        float var  = sq * inv_d - mean * mean;
        float inv  = rsqrtf(var + 1e-9f);

        float4 res;
        res.x = scv.x * (vw.x - mean) * inv + offv.x;
        res.y = scv.y * (vw.y - mean) * inv + offv.y;
        res.z = scv.z * (vw.z - mean) * inv + offv.z;
        res.w = scv.w * (vw.w - mean) * inv + offv.w;

        if (row < n_rows) {
            float4* po = (float4*)&out[(size_t)row * D + tx * 4];
            if (accumulate) {
                float4 cur = *po;
                res.x += cur.x; res.y += cur.y; res.z += cur.z; res.w += cur.w;
            }
            *po = res;
        }
    }
}

// ---------------------------------------------------------------------------
extern "C" void kernel_launch(void* const* d_in, const int* in_sizes, int n_in,
                              void* d_out, int out_size) {
    const float* vecs = (const float*)d_in[0];
    const float* vals = (const float*)d_in[1];
    const int*   row  = (const int*)d_in[2];
    const int*   col  = (const int*)d_in[3];
    const float* W0 = (const float*)d_in[4];
    const float* b0 = (const float*)d_in[5];
    const float* off0 = (const float*)d_in[6];
    const float* sc0  = (const float*)d_in[7];
    const float* W1 = (const float*)d_in[8];
    const float* b1 = (const float*)d_in[9];
    const float* off1 = (const float*)d_in[10];
    const float* sc1  = (const float*)d_in[11];
    const float* W2 = (const float*)d_in[12];
    const float* b2 = (const float*)d_in[13];
    const float* off2 = (const float*)d_in[14];
    const float* sc2  = (const float*)d_in[15];
    float* out = (float*)d_out;

    const int n_edges = in_sizes[1];
    const int n_rows  = in_sizes[0] / D;

    float *hop1, *hop2;
    cudaGetSymbolAddress((void**)&hop1, g_hop1);
    cudaGetSymbolAddress((void**)&hop2, g_hop2);
    cudaFuncSetAttribute(gemm_norm_kernel,
                         cudaFuncAttributeMaxDynamicSharedMemorySize, GEMM_SMEM);

    const size_t hop_bytes = (size_t)n_rows * D * sizeof(float);
    cudaMemsetAsync(hop1, 0, hop_bytes);
    cudaMemsetAsync(hop2, 0, hop_bytes);

    const int spmm_threads = 256;
    const long long total = (long long)n_edges * 32;
    const int spmm_blocks = (int)((total + spmm_threads - 1) / spmm_threads);

    spmm_scatter_kernel<<<spmm_blocks, spmm_threads>>>(vecs, hop1, vals, row, col, n_edges);
    spmm_scatter_kernel<<<spmm_blocks, spmm_threads>>>(hop1, hop2, vals, row, col, n_edges);

    const int gemm_blocks = (n_rows + TILE_ROWS - 1) / TILE_ROWS;
    dim3 gb(32, 8);
    gemm_norm_kernel<<<gemm_blocks, gb, GEMM_SMEM>>>(vecs, W0, b0, off0, sc0, out, n_rows, 0);
    gemm_norm_kernel<<<gemm_blocks, gb, GEMM_SMEM>>>(hop1, W1, b1, off1, sc1, out, n_rows, 1);
    gemm_norm_kernel<<<gemm_blocks, gb, GEMM_SMEM>>>(hop2, W2, b2, off2, sc2, out, n_rows, 1);
}

// round 3
// speedup vs baseline: 1.6235x; 1.5264x over previous
#include <cuda_runtime.h>

#define D 128
#define MAX_N 100000
#define MAX_E 1600000
#define TILE_ROWS 64
#define GEMM_SMEM ((D*D + TILE_ROWS*D) * (int)sizeof(float))  // 96 KB
#define SCAN_BLK 512

// Scratch (allocation-free rule: __device__ globals)
__device__ float g_hop1[(size_t)MAX_N * D];
__device__ float g_hop2[(size_t)MAX_N * D];
__device__ int   g_cnt[MAX_N];
__device__ int   g_rs[MAX_N + 1];        // CSR row_start
__device__ int   g_cursor[MAX_N];
__device__ int   g_bsum[1024];
__device__ int   g_ccol[MAX_E];
__device__ float g_cval[MAX_E];

// ---------------------------------------------------------------------------
// Packed fp32x2 helpers (sm_103a: fma.rn.f32x2 — 2 fp32 FMAs per fma-pipe slot)
// ---------------------------------------------------------------------------
__device__ __forceinline__ unsigned long long ffma2(unsigned long long a,
                                                    unsigned long long b,
                                                    unsigned long long c) {
    unsigned long long d;
    asm("fma.rn.f32x2 %0, %1, %2, %3;" : "=l"(d) : "l"(a), "l"(b), "l"(c));
    return d;
}
__device__ __forceinline__ unsigned long long splat2(float x) {
    unsigned long long d;
    asm("mov.b64 %0, {%1, %1};" : "=l"(d) : "f"(x));
    return d;
}
__device__ __forceinline__ float2 unpack2(unsigned long long v) {
    float lo, hi;
    asm("mov.b64 {%0, %1}, %2;" : "=f"(lo), "=f"(hi) : "l"(v));
    return make_float2(lo, hi);
}

// ---------------------------------------------------------------------------
// CSR construction: histogram -> block scan -> offsets -> scatter
// ---------------------------------------------------------------------------
__global__ void hist_kernel(const int* __restrict__ row, int n_edges,
                            int* __restrict__ cnt) {
    int e = blockIdx.x * blockDim.x + threadIdx.x;
    if (e < n_edges) atomicAdd(&cnt[row[e]], 1);
}

__global__ void scan_block_kernel(const int* __restrict__ cnt,
                                  int* __restrict__ rs,
                                  int* __restrict__ bsum, int n) {
    __shared__ int sh[SCAN_BLK];
    int i = blockIdx.x * SCAN_BLK + threadIdx.x;
    int v = (i < n) ? cnt[i] : 0;
    sh[threadIdx.x] = v;
    __syncthreads();
    #pragma unroll
    for (int o = 1; o < SCAN_BLK; o <<= 1) {
        int t = (threadIdx.x >= o) ? sh[threadIdx.x - o] : 0;
        __syncthreads();
        sh[threadIdx.x] += t;
        __syncthreads();
    }
    int incl = sh[threadIdx.x];
    if (i < n) rs[i] = incl - v;                 // block-local exclusive
    if (threadIdx.x == SCAN_BLK - 1) bsum[blockIdx.x] = incl;
}

__global__ void scan_bsum_kernel(int* __restrict__ bsum, int nb) {
    __shared__ int sh[1024];
    int v = (threadIdx.x < nb) ? bsum[threadIdx.x] : 0;
    sh[threadIdx.x] = v;
    __syncthreads();
    #pragma unroll
    for (int o = 1; o < 1024; o <<= 1) {
        int t = (threadIdx.x >= o) ? sh[threadIdx.x - o] : 0;
        __syncthreads();
        sh[threadIdx.x] += t;
        __syncthreads();
    }
    if (threadIdx.x < nb) bsum[threadIdx.x] = sh[threadIdx.x] - v;  // exclusive
}

__global__ void scan_add_kernel(int* __restrict__ rs,
                                const int* __restrict__ bsum,
                                int* __restrict__ cursor, int n, int total) {
    int i = blockIdx.x * blockDim.x + threadIdx.x;
    if (i < n) {
        int v = rs[i] + bsum[i >> 9];            // SCAN_BLK == 512
        rs[i] = v;
        cursor[i] = v;
    }
    if (i == n) rs[n] = total;
}

__global__ void scatter_kernel(const int* __restrict__ row,
                               const int* __restrict__ col,
                               const float* __restrict__ vals, int n_edges,
                               int* __restrict__ cursor,
                               int* __restrict__ ccol,
                               float* __restrict__ cval) {
    int e = blockIdx.x * blockDim.x + threadIdx.x;
    if (e >= n_edges) return;
    int r = row[e];
    int p = atomicAdd(&cursor[r], 1);
    ccol[p] = col[e];
    cval[p] = vals[e];
}

// ---------------------------------------------------------------------------
// Gather SpMM: y[r] = sum_{j in row r} cval[j] * x[ccol[j]]
// One warp per row; lane owns a float4 (32 lanes * 4 = 128 cols).
// Unroll 4 for MLP. Single coalesced write per row, no atomics, no zeroing.
// ---------------------------------------------------------------------------
__global__ void __launch_bounds__(256)
spmm_gather_kernel(const float* __restrict__ x,
                   float* __restrict__ y,
                   const int* __restrict__ rs,
                   const int* __restrict__ ccol,
                   const float* __restrict__ cval,
                   int n_rows) {
    int w    = (blockIdx.x * blockDim.x + threadIdx.x) >> 5;
    int lane = threadIdx.x & 31;
    if (w >= n_rows) return;

    int s = __ldg(&rs[w]);
    int e = __ldg(&rs[w + 1]);

    float4 acc = make_float4(0.f, 0.f, 0.f, 0.f);
    int j = s;
    for (; j + 3 < e; j += 4) {
        int   c0 = __ldg(&ccol[j]),     c1 = __ldg(&ccol[j + 1]);
        int   c2 = __ldg(&ccol[j + 2]), c3 = __ldg(&ccol[j + 3]);
        float v0 = __ldg(&cval[j]),     v1 = __ldg(&cval[j + 1]);
        float v2 = __ldg(&cval[j + 2]), v3 = __ldg(&cval[j + 3]);
        float4 x0 = ((const float4*)x)[(size_t)c0 * (D / 4) + lane];
        float4 x1 = ((const float4*)x)[(size_t)c1 * (D / 4) + lane];
        float4 x2 = ((const float4*)x)[(size_t)c2 * (D / 4) + lane];
        float4 x3 = ((const float4*)x)[(size_t)c3 * (D / 4) + lane];
        acc.x = fmaf(v0, x0.x, fmaf(v1, x1.x, fmaf(v2, x2.x, fmaf(v3, x3.x, acc.x))));
        acc.y = fmaf(v0, x0.y, fmaf(v1, x1.y, fmaf(v2, x2.y, fmaf(v3, x3.y, acc.y))));
        acc.z = fmaf(v0, x0.z, fmaf(v1, x1.z, fmaf(v2, x2.z, fmaf(v3, x3.z, acc.z))));
        acc.w = fmaf(v0, x0.w, fmaf(v1, x1.w, fmaf(v2, x2.w, fmaf(v3, x3.w, acc.w))));
    }
    for (; j < e; j++) {
        int   c = __ldg(&ccol[j]);
        float v = __ldg(&cval[j]);
        float4 xv = ((const float4*)x)[(size_t)c * (D / 4) + lane];
        acc.x = fmaf(v, xv.x, acc.x);
        acc.y = fmaf(v, xv.y, acc.y);
        acc.z = fmaf(v, xv.z, acc.z);
        acc.w = fmaf(v, xv.w, acc.w);
    }
    ((float4*)y)[(size_t)w * (D / 4) + lane] = acc;
}

// ---------------------------------------------------------------------------
// Fused GEMM + bias + relu + per-row moment-norm + affine (+ accumulate).
// (unchanged from R2 — near f32x2 scalar ceiling)
// ---------------------------------------------------------------------------
__global__ void __launch_bounds__(256, 2)
gemm_norm_kernel(const float* __restrict__ V,
                 const float* __restrict__ W,
                 const float* __restrict__ b,
                 const float* __restrict__ off,
                 const float* __restrict__ sc,
                 float* __restrict__ out,
                 int n_rows, int accumulate) {
    extern __shared__ float sh[];
    float* Wsh = sh;                  // 128 x 128
    float* Vsh = sh + D * D;          // 64 x 128

    const int tx  = threadIdx.x;      // 0..31  (col quad)
    const int ty  = threadIdx.y;      // 0..7   (row group)
    const int tid = ty * 32 + tx;
    const int row0 = blockIdx.x * TILE_ROWS;

    #pragma unroll
    for (int i = tid; i < D * D / 4; i += 256)
        ((float4*)Wsh)[i] = ((const float4*)W)[i];

    for (int i = tid; i < TILE_ROWS * (D / 4); i += 256) {
        int r = i >> 5, c = i & 31;
        float4 v;
        if (row0 + r < n_rows)
            v = ((const float4*)V)[(size_t)(row0 + r) * (D / 4) + c];
        else
            v = make_float4(0.f, 0.f, 0.f, 0.f);
        ((float4*)Vsh)[r * (D / 4) + c] = v;
    }
    __syncthreads();

    unsigned long long acc[8][2];
    #pragma unroll
    for (int r = 0; r < 8; r++) { acc[r][0] = 0ull; acc[r][1] = 0ull; }

    #pragma unroll 4
    for (int k4 = 0; k4 < D / 4; k4++) {
        float4 vv[8];
        #pragma unroll
        for (int r = 0; r < 8; r++)
            vv[r] = *(const float4*)&Vsh[(ty * 8 + r) * D + k4 * 4];

        #pragma unroll
        for (int kk = 0; kk < 4; kk++) {
            const ulonglong2 w2 = *(const ulonglong2*)&Wsh[(k4 * 4 + kk) * D + tx * 4];
            #pragma unroll
            for (int r = 0; r < 8; r++) {
                float v = (kk == 0) ? vv[r].x : (kk == 1) ? vv[r].y
                        : (kk == 2) ? vv[r].z : vv[r].w;
                unsigned long long vp = splat2(v);
                acc[r][0] = ffma2(vp, w2.x, acc[r][0]);
                acc[r][1] = ffma2(vp, w2.y, acc[r][1]);
            }
        }
    }

    const float4 bv   = ((const float4*)b)[tx];
    const float4 scv  = ((const float4*)sc)[tx];
    const float4 offv = ((const float4*)off)[tx];
    const float inv_d = 1.0f / (float)D;

    #pragma unroll
    for (int r = 0; r < 8; r++) {
        int row = row0 + ty * 8 + r;

        float2 a01 = unpack2(acc[r][0]);
        float2 a23 = unpack2(acc[r][1]);

        float4 vw;
        vw.x = fmaxf(a01.x + bv.x, 0.f);
        vw.y = fmaxf(a01.y + bv.y, 0.f);
        vw.z = fmaxf(a23.x + bv.z, 0.f);
        vw.w = fmaxf(a23.y + bv.w, 0.f);

        float s  = vw.x + vw.y + vw.z + vw.w;
        float sq = vw.x * vw.x + vw.y * vw.y + vw.z * vw.z + vw.w * vw.w;
        #pragma unroll
        for (int o = 16; o > 0; o >>= 1) {
            s  += __shfl_xor_sync(0xffffffffu, s,  o);
            sq += __shfl_xor_sync(0xffffffffu, sq, o);
        }

        float mean = s * inv_d;
        float var  = sq * inv_d - mean * mean;
        float inv  = rsqrtf(var + 1e-9f);

        float4 res;
        res.x = scv.x * (vw.x - mean) * inv + offv.x;
        res.y = scv.y * (vw.y - mean) * inv + offv.y;
        res.z = scv.z * (vw.z - mean) * inv + offv.z;
        res.w = scv.w * (vw.w - mean) * inv + offv.w;

        if (row < n_rows) {
            float4* po = (float4*)&out[(size_t)row * D + tx * 4];
            if (accumulate) {
                float4 cur = *po;
                res.x += cur.x; res.y += cur.y; res.z += cur.z; res.w += cur.w;
            }
            *po = res;
        }
    }
}

// ---------------------------------------------------------------------------
extern "C" void kernel_launch(void* const* d_in, const int* in_sizes, int n_in,
                              void* d_out, int out_size) {
    const float* vecs = (const float*)d_in[0];
    const float* vals = (const float*)d_in[1];
    const int*   row  = (const int*)d_in[2];
    const int*   col  = (const int*)d_in[3];
    const float* W0 = (const float*)d_in[4];
    const float* b0 = (const float*)d_in[5];
    const float* off0 = (const float*)d_in[6];
    const float* sc0  = (const float*)d_in[7];
    const float* W1 = (const float*)d_in[8];
    const float* b1 = (const float*)d_in[9];
    const float* off1 = (const float*)d_in[10];
    const float* sc1  = (const float*)d_in[11];
    const float* W2 = (const float*)d_in[12];
    const float* b2 = (const float*)d_in[13];
    const float* off2 = (const float*)d_in[14];
    const float* sc2  = (const float*)d_in[15];
    float* out = (float*)d_out;

    const int n_edges = in_sizes[1];
    const int n_rows  = in_sizes[0] / D;

    float *hop1, *hop2, *cval;
    int *cnt, *rs, *cursor, *bsum, *ccol;
    cudaGetSymbolAddress((void**)&hop1,   g_hop1);
    cudaGetSymbolAddress((void**)&hop2,   g_hop2);
    cudaGetSymbolAddress((void**)&cnt,    g_cnt);
    cudaGetSymbolAddress((void**)&rs,     g_rs);
    cudaGetSymbolAddress((void**)&cursor, g_cursor);
    cudaGetSymbolAddress((void**)&bsum,   g_bsum);
    cudaGetSymbolAddress((void**)&ccol,   g_ccol);
    cudaGetSymbolAddress((void**)&cval,   g_cval);
    cudaFuncSetAttribute(gemm_norm_kernel,
                         cudaFuncAttributeMaxDynamicSharedMemorySize, GEMM_SMEM);

    // ---- CSR build (graph identical for both hops) ----
    cudaMemsetAsync(cnt, 0, (size_t)n_rows * sizeof(int));
    const int eb = (n_edges + 255) / 256;
    hist_kernel<<<eb, 256>>>(row, n_edges, cnt);

    const int nb = (n_rows + SCAN_BLK - 1) / SCAN_BLK;   // <= 1024 required
    scan_block_kernel<<<nb, SCAN_BLK>>>(cnt, rs, bsum, n_rows);
    scan_bsum_kernel<<<1, 1024>>>(bsum, nb);
    scan_add_kernel<<<(n_rows + 256) / 256, 256>>>(rs, bsum, cursor, n_rows, n_edges);
    scatter_kernel<<<eb, 256>>>(row, col, vals, n_edges, cursor, ccol, cval);

    // ---- 2-hop gather SpMM ----
    const int gw_blocks = (n_rows * 32 + 255) / 256;
    spmm_gather_kernel<<<gw_blocks, 256>>>(vecs, hop1, rs, ccol, cval, n_rows);
    spmm_gather_kernel<<<gw_blocks, 256>>>(hop1, hop2, rs, ccol, cval, n_rows);

    // ---- 3 fused GEMM+norm ----
    const int gemm_blocks = (n_rows + TILE_ROWS - 1) / TILE_ROWS;
    dim3 gb(32, 8);
    gemm_norm_kernel<<<gemm_blocks, gb, GEMM_SMEM>>>(vecs, W0, b0, off0, sc0, out, n_rows, 0);
    gemm_norm_kernel<<<gemm_blocks, gb, GEMM_SMEM>>>(hop1, W1, b1, off1, sc1, out, n_rows, 1);
    gemm_norm_kernel<<<gemm_blocks, gb, GEMM_SMEM>>>(hop2, W2, b2, off2, sc2, out, n_rows, 1);
}